// round 11
// baseline (speedup 1.0000x reference)
#include <cuda_runtime.h>
#include <cuda_fp16.h>

// Problem constants
#define NB 4096
#define NT 512
#define NC 4
#define NH 32
#define NO 3

// One warp = 16 batch rows, whole hidden state in MMA accumulators.
#define ROWS_PER_WARP 16
#define NBLOCKS (NB / ROWS_PER_WARP)   // 256

__device__ __forceinline__ unsigned h2u(float lo, float hi) {
    __half2 h = __floats2half2_rn(lo, hi);   // x = lo half, y = hi half
    return *reinterpret_cast<unsigned*>(&h);
}
__device__ __forceinline__ float h2lo(unsigned u) {
    __half2 h = *reinterpret_cast<__half2*>(&u);
    return __low2float(h);
}
__device__ __forceinline__ float h2hi(unsigned u) {
    __half2 h = *reinterpret_cast<__half2*>(&u);
    return __high2float(h);
}

// D = A*B + D   (m16n8k16, f16 inputs, f32 accumulate)
__device__ __forceinline__ void mma_acc(float& d0, float& d1, float& d2, float& d3,
                                        unsigned a0, unsigned a1, unsigned a2, unsigned a3,
                                        unsigned b0, unsigned b1) {
    asm volatile(
        "mma.sync.aligned.m16n8k16.row.col.f32.f16.f16.f32 "
        "{%0,%1,%2,%3}, {%4,%5,%6,%7}, {%8,%9}, {%0,%1,%2,%3};"
        : "+f"(d0), "+f"(d1), "+f"(d2), "+f"(d3)
        : "r"(a0), "r"(a1), "r"(a2), "r"(a3), "r"(b0), "r"(b1));
}
// D = A*B  (C = 0)
__device__ __forceinline__ void mma_zro(float& d0, float& d1, float& d2, float& d3,
                                        unsigned a0, unsigned a1, unsigned a2, unsigned a3,
                                        unsigned b0, unsigned b1) {
    asm volatile(
        "mma.sync.aligned.m16n8k16.row.col.f32.f16.f16.f32 "
        "{%0,%1,%2,%3}, {%4,%5,%6,%7}, {%8,%9}, {%10,%10,%10,%10};"
        : "=f"(d0), "=f"(d1), "=f"(d2), "=f"(d3)
        : "r"(a0), "r"(a1), "r"(a2), "r"(a3), "r"(b0), "r"(b1), "f"(0.0f));
}

__global__ void __launch_bounds__(32)
rnn_mma_kernel(const float* __restrict__ seq,
               const float* __restrict__ w_ih,
               const float* __restrict__ w_hh,
               const float* __restrict__ b_ih,
               const float* __restrict__ b_hh,
               const float* __restrict__ fc_w,
               const float* __restrict__ fc_b,
               float* __restrict__ out) {
    const int tid = threadIdx.x;
    const int gr  = tid >> 2;            // 0..7 (row group)
    const int c   = tid & 3;             // 0..3 (col group)
    const int rowbase = blockIdx.x * ROWS_PER_WARP;
    const int rA = rowbase + gr;         // rows gr and gr+8 of the 16-row tile
    const int rB = rowbase + gr + 8;
    const bool lt2 = (c < 2);

    // ---- B fragments for W_hh^T (k=hidden-in, n=hidden-out), hi/lo split ----
    // b0 = (B[k0][n], B[k0+1][n]),  b1 = (B[k0+8][n], B[k0+9][n]),  n = 8*nt+gr
    unsigned bhh_hi[2][4][2], bhh_lo[2][4][2];
#pragma unroll
    for (int kc = 0; kc < 2; kc++) {
#pragma unroll
        for (int nt = 0; nt < 4; nt++) {
            const int n  = 8 * nt + gr;
            const int k0 = 16 * kc + 2 * c;
            float w[4] = { w_hh[n * NH + k0],     w_hh[n * NH + k0 + 1],
                           w_hh[n * NH + k0 + 8], w_hh[n * NH + k0 + 9] };
            float wh[4], wl[4];
#pragma unroll
            for (int i = 0; i < 4; i++) {
                wh[i] = __half2float(__float2half_rn(w[i]));
                wl[i] = w[i] - wh[i];
            }
            bhh_hi[kc][nt][0] = h2u(wh[0], wh[1]);
            bhh_hi[kc][nt][1] = h2u(wh[2], wh[3]);
            bhh_lo[kc][nt][0] = h2u(wl[0], wl[1]);
            bhh_lo[kc][nt][1] = h2u(wl[2], wl[3]);
        }
    }

    // ---- B fragments for x_proj: k-rows 0..3 = w_ih^T, k-row 4 = bias ----
    unsigned bih_hi[4], bih_lo[4];
#pragma unroll
    for (int nt = 0; nt < 4; nt++) {
        const int n = 8 * nt + gr;
        float v[2];
#pragma unroll
        for (int i = 0; i < 2; i++) {
            const int k = 2 * c + i;
            v[i] = (k < NC) ? w_ih[n * NC + k]
                            : ((k == NC) ? (b_ih[n] + b_hh[n]) : 0.0f);
        }
        const float vh0 = __half2float(__float2half_rn(v[0]));
        const float vh1 = __half2float(__float2half_rn(v[1]));
        bih_hi[nt] = h2u(vh0, vh1);
        bih_lo[nt] = h2u(v[0] - vh0, v[1] - vh1);
    }
    const unsigned zero_b = 0u;
    // seq A-frag constant for c>=2: A-col 4 = 1.0 (bias multiplier), rest 0
    const unsigned aconst = (c == 2) ? h2u(1.0f, 0.0f) : 0u;

    // seq pointers: thread c<2 loads float2 = cols {2c,2c+1} of its rows
    const float2* pA = reinterpret_cast<const float2*>(seq + (size_t)rA * (NT * NC));
    const float2* pB = reinterpret_cast<const float2*>(seq + (size_t)rB * (NT * NC));
    const float2 f2z = make_float2(0.f, 0.f);
    float2 sA0 = lt2 ? pA[c]     : f2z;
    float2 sB0 = lt2 ? pB[c]     : f2z;
    float2 sA1 = lt2 ? pA[2 + c] : f2z;
    float2 sB1 = lt2 ? pB[2 + c] : f2z;

    // hidden state as A fragments (hi/lo split); h(0) = 0
    unsigned ahi[2][4] = {{0u,0u,0u,0u},{0u,0u,0u,0u}};
    unsigned alo[2][4] = {{0u,0u,0u,0u},{0u,0u,0u,0u}};
    float d0[4], d1[4], d2[4], d3[4];   // accumulators, 4 n-tiles

    for (int t = 0; t < NT; t++) {
        const float2 cA = sA0;  sA0 = sA1;
        const float2 cB = sB0;  sB0 = sB1;
        const int tn = (t + 2 < NT) ? (t + 2) : (NT - 1);
        sA1 = lt2 ? pA[2 * tn + c] : f2z;
        sB1 = lt2 ? pB[2 * tn + c] : f2z;

        const unsigned as0 = lt2 ? h2u(cA.x, cA.y) : aconst;  // row gr
        const unsigned as1 = lt2 ? h2u(cB.x, cB.y) : aconst;  // row gr+8

        // x_proj + bias:  D = Aseq*Bih_hi ;  D += Aseq*Bih_lo
#pragma unroll
        for (int nt = 0; nt < 4; nt++)
            mma_zro(d0[nt], d1[nt], d2[nt], d3[nt],
                    as0, as1, 0u, 0u, bih_hi[nt], zero_b);
#pragma unroll
        for (int nt = 0; nt < 4; nt++)
            mma_acc(d0[nt], d1[nt], d2[nt], d3[nt],
                    as0, as1, 0u, 0u, bih_lo[nt], zero_b);

        // recurrence: Ahi*Bhi + Alo*Bhi + Ahi*Blo  (residual ~2^-22)
#pragma unroll
        for (int kc = 0; kc < 2; kc++)
#pragma unroll
            for (int nt = 0; nt < 4; nt++)
                mma_acc(d0[nt], d1[nt], d2[nt], d3[nt],
                        ahi[kc][0], ahi[kc][1], ahi[kc][2], ahi[kc][3],
                        bhh_hi[kc][nt][0], bhh_hi[kc][nt][1]);
#pragma unroll
        for (int kc = 0; kc < 2; kc++)
#pragma unroll
            for (int nt = 0; nt < 4; nt++)
                mma_acc(d0[nt], d1[nt], d2[nt], d3[nt],
                        alo[kc][0], alo[kc][1], alo[kc][2], alo[kc][3],
                        bhh_hi[kc][nt][0], bhh_hi[kc][nt][1]);
#pragma unroll
        for (int kc = 0; kc < 2; kc++)
#pragma unroll
            for (int nt = 0; nt < 4; nt++)
                mma_acc(d0[nt], d1[nt], d2[nt], d3[nt],
                        ahi[kc][0], ahi[kc][1], ahi[kc][2], ahi[kc][3],
                        bhh_lo[kc][nt][0], bhh_lo[kc][nt][1]);

        // relu (exact, fp32, in place — after loop these are h_T for the FC)
#pragma unroll
        for (int nt = 0; nt < 4; nt++) {
            d0[nt] = fmaxf(d0[nt], 0.0f);
            d1[nt] = fmaxf(d1[nt], 0.0f);
            d2[nt] = fmaxf(d2[nt], 0.0f);
            d3[nt] = fmaxf(d3[nt], 0.0f);
        }

        // D -> A: native layout identity. k-chunk kc consumes n-tiles 2kc, 2kc+1.
#pragma unroll
        for (int kc = 0; kc < 2; kc++) {
            const int u = 2 * kc, v = 2 * kc + 1;
            unsigned h;
            h = h2u(d0[u], d1[u]); ahi[kc][0] = h;
            alo[kc][0] = h2u(d0[u] - h2lo(h), d1[u] - h2hi(h));
            h = h2u(d2[u], d3[u]); ahi[kc][1] = h;
            alo[kc][1] = h2u(d2[u] - h2lo(h), d3[u] - h2hi(h));
            h = h2u(d0[v], d1[v]); ahi[kc][2] = h;
            alo[kc][2] = h2u(d0[v] - h2lo(h), d1[v] - h2hi(h));
            h = h2u(d2[v], d3[v]); ahi[kc][3] = h;
            alo[kc][3] = h2u(d2[v] - h2lo(h), d3[v] - h2hi(h));
        }
    }

    // ---- FC head: d regs hold h_T at [gr / gr+8][8nt + 2c, 2c+1] ----
#pragma unroll
    for (int o = 0; o < NO; o++) {
        float accA = 0.f, accB = 0.f;
#pragma unroll
        for (int nt = 0; nt < 4; nt++) {
            const float fw0 = fc_w[o * NH + 8 * nt + 2 * c];
            const float fw1 = fc_w[o * NH + 8 * nt + 2 * c + 1];
            accA = fmaf(d0[nt], fw0, fmaf(d1[nt], fw1, accA));
            accB = fmaf(d2[nt], fw0, fmaf(d3[nt], fw1, accB));
        }
        accA += __shfl_xor_sync(0xffffffffu, accA, 1);
        accA += __shfl_xor_sync(0xffffffffu, accA, 2);
        accB += __shfl_xor_sync(0xffffffffu, accB, 1);
        accB += __shfl_xor_sync(0xffffffffu, accB, 2);
        if (c == 0) {
            out[rA * NO + o] = accA + fc_b[o];
            out[rB * NO + o] = accB + fc_b[o];
        }
    }
}

extern "C" void kernel_launch(void* const* d_in, const int* in_sizes, int n_in,
                              void* d_out, int out_size) {
    const float* seq  = (const float*)d_in[0];
    const float* w_ih = (const float*)d_in[1];
    const float* w_hh = (const float*)d_in[2];
    const float* b_ih = (const float*)d_in[3];
    const float* b_hh = (const float*)d_in[4];
    const float* fc_w = (const float*)d_in[5];
    const float* fc_b = (const float*)d_in[6];
    float* out = (float*)d_out;

    rnn_mma_kernel<<<NBLOCKS, 32>>>(seq, w_ih, w_hh, b_ih, b_hh,
                                    fc_w, fc_b, out);
}